// round 1
// baseline (speedup 1.0000x reference)
#include <cuda_runtime.h>
#include <cuda_bf16.h>
#include <cstdint>

#define BATCH 2048
#define VOCAB 50000
#define EMB   100
#define CTX   10
#define KP    112      // EMB padded to multiple of 16 for mma.sync k-steps
#define VP    50048    // VOCAB padded to multiple of 64 (= 782*64)
#define BM    128
#define BN    64
#define SSTR  120      // smem row stride in bf16 elems (240B, conflict-free frag loads)

// Scratch (device globals; zero-initialized at module load, rows >= VOCAB stay 0)
__device__ __align__(16) float          g_h[BATCH * EMB];
__device__ __align__(16) __nv_bfloat16  g_hb[BATCH * KP];
__device__ __align__(16) __nv_bfloat16  g_ub[VP * KP];
__device__ float                        g_negsum[BATCH];
__device__ float                        g_perb[BATCH];

__device__ __forceinline__ float tanh_approx(float x) {
    float y;
    asm("tanh.approx.f32 %0, %1;" : "=f"(y) : "f"(x));
    return y;
}

// ---------------------------------------------------------------------------
// K0: h[b] = mean over CTX of emb_v rows; also bf16 copy (padded) + zero negsum
// ---------------------------------------------------------------------------
__global__ void k_h(const int* __restrict__ x, const float* __restrict__ emb_v) {
    int b = blockIdx.x;
    int t = threadIdx.x;  // 128 threads
    __shared__ int ctx[CTX];
    if (t < CTX) ctx[t] = x[b * CTX + t];
    __syncthreads();
    if (t == 0) g_negsum[b] = 0.0f;
    if (t < KP) {
        float s = 0.0f;
        if (t < EMB) {
#pragma unroll
            for (int c = 0; c < CTX; c++) s += emb_v[(size_t)ctx[c] * EMB + t];
            s *= 0.1f;
            g_h[b * EMB + t] = s;
        }
        g_hb[b * KP + t] = __float2bfloat16(t < EMB ? s : 0.0f);
    }
}

// ---------------------------------------------------------------------------
// K1: emb_u -> bf16, padded [VP][KP] (zeros in pad region)
// ---------------------------------------------------------------------------
__global__ void k_u(const float* __restrict__ emb_u) {
    int i = blockIdx.x * blockDim.x + threadIdx.x;  // VP*KP = 5,605,376 < 2^31
    if (i >= VP * KP) return;
    int v = i / KP, k = i % KP;
    float val = (v < VOCAB && k < EMB) ? emb_u[(size_t)v * EMB + k] : 0.0f;
    g_ub[i] = __float2bfloat16(val);
}

// ---------------------------------------------------------------------------
// K2: fused GEMM (scores = h @ U^T) + sigmoid-sum over vocab via tanh identity
//     block tile: 128(M=batch) x 64(N=vocab), K=112 in one shot (fits smem)
//     8 warps = 4(M) x 2(N); warp tile 32x32; mma.sync m16n8k16 bf16->f32
// ---------------------------------------------------------------------------
__global__ __launch_bounds__(256) void k_gemm() {
    __shared__ __nv_bfloat16 sA[BM * SSTR];   // 30720 B
    __shared__ __nv_bfloat16 sB[BN * SSTR];   // 15360 B
    int t = threadIdx.x;
    int mbase = blockIdx.y * BM;
    int nbase = blockIdx.x * BN;

    // Load A tile (128 rows x 112 bf16 = 14 uint4 per row)
    const uint4* gA = (const uint4*)(g_hb + (size_t)mbase * KP);
#pragma unroll
    for (int i = 0; i < 7; i++) {
        int idx = t + i * 256;
        int r = idx / 14, c = idx % 14;
        *(uint4*)&sA[r * SSTR + c * 8] = gA[r * 14 + c];
    }
    // Load B tile (64 rows x 14 uint4)
    const uint4* gB = (const uint4*)(g_ub + (size_t)nbase * KP);
#pragma unroll
    for (int i = 0; i < 4; i++) {
        int idx = t + i * 256;
        if (idx < BN * 14) {
            int r = idx / 14, c = idx % 14;
            *(uint4*)&sB[r * SSTR + c * 8] = gB[r * 14 + c];
        }
    }
    __syncthreads();

    int warp = t >> 5, lane = t & 31;
    int gid = lane >> 2, tig = lane & 3;
    int mw = warp >> 1;              // 0..3 -> 32-row slice
    int nw = warp & 1;               // 0..1 -> 32-col slice
    int arow0 = mw * 32;
    int brow0 = nw * 32;

    float acc[2][4][4];
#pragma unroll
    for (int im = 0; im < 2; im++)
#pragma unroll
        for (int in = 0; in < 4; in++)
#pragma unroll
            for (int q = 0; q < 4; q++) acc[im][in][q] = 0.0f;

#pragma unroll
    for (int ks = 0; ks < 7; ks++) {
        int k0 = ks * 16;
        uint32_t a[2][4], bb[4][2];
#pragma unroll
        for (int im = 0; im < 2; im++) {
            int r0 = arow0 + im * 16 + gid;
            a[im][0] = *(const uint32_t*)&sA[(r0    ) * SSTR + k0     + 2 * tig];
            a[im][1] = *(const uint32_t*)&sA[(r0 + 8) * SSTR + k0     + 2 * tig];
            a[im][2] = *(const uint32_t*)&sA[(r0    ) * SSTR + k0 + 8 + 2 * tig];
            a[im][3] = *(const uint32_t*)&sA[(r0 + 8) * SSTR + k0 + 8 + 2 * tig];
        }
#pragma unroll
        for (int in = 0; in < 4; in++) {
            int rn = brow0 + in * 8 + gid;
            bb[in][0] = *(const uint32_t*)&sB[rn * SSTR + k0     + 2 * tig];
            bb[in][1] = *(const uint32_t*)&sB[rn * SSTR + k0 + 8 + 2 * tig];
        }
#pragma unroll
        for (int im = 0; im < 2; im++)
#pragma unroll
            for (int in = 0; in < 4; in++)
                asm volatile(
                    "mma.sync.aligned.m16n8k16.row.col.f32.bf16.bf16.f32 "
                    "{%0,%1,%2,%3}, {%4,%5,%6,%7}, {%8,%9}, {%0,%1,%2,%3};"
                    : "+f"(acc[im][in][0]), "+f"(acc[im][in][1]),
                      "+f"(acc[im][in][2]), "+f"(acc[im][in][3])
                    : "r"(a[im][0]), "r"(a[im][1]), "r"(a[im][2]), "r"(a[im][3]),
                      "r"(bb[in][0]), "r"(bb[in][1]));
    }

    // Epilogue: term = sigmoid(-score) = 0.5 - 0.5*tanh(score/2); mask pad cols
    float rs[2][2] = {{0.0f, 0.0f}, {0.0f, 0.0f}};
#pragma unroll
    for (int im = 0; im < 2; im++)
#pragma unroll
        for (int in = 0; in < 4; in++)
#pragma unroll
            for (int q = 0; q < 4; q++) {
                int n = nbase + brow0 + in * 8 + 2 * tig + (q & 1);
                if (n < VOCAB) {
                    float th = tanh_approx(0.5f * acc[im][in][q]);
                    rs[im][q >> 1] += 0.5f - 0.5f * th;
                }
            }
#pragma unroll
    for (int im = 0; im < 2; im++)
#pragma unroll
        for (int h = 0; h < 2; h++) {
            float vsum = rs[im][h];
            vsum += __shfl_xor_sync(0xffffffff, vsum, 1);
            vsum += __shfl_xor_sync(0xffffffff, vsum, 2);
            if (tig == 0) {
                int row = mbase + arow0 + im * 16 + h * 8 + gid;
                atomicAdd(&g_negsum[row], vsum);
            }
        }
}

// ---------------------------------------------------------------------------
// K3: per-b: pos = -log_sigmoid(dot(emb_u[y], h)); perb = pos + log(negsum)
// ---------------------------------------------------------------------------
__global__ void k_perb(const int* __restrict__ y, const float* __restrict__ emb_u) {
    int gwarp = (blockIdx.x * blockDim.x + threadIdx.x) >> 5;
    int lane = threadIdx.x & 31;
    if (gwarp >= BATCH) return;
    int b = gwarp;
    const float* u = emb_u + (size_t)y[b] * EMB;
    const float* h = g_h + (size_t)b * EMB;
    float d = 0.0f;
    for (int e = lane; e < EMB; e += 32) d += u[e] * h[e];
#pragma unroll
    for (int o = 16; o; o >>= 1) d += __shfl_xor_sync(0xffffffff, d, o);
    if (lane == 0) {
        // stable log_sigmoid
        float ls = (d >= 0.0f) ? -log1pf(expf(-d)) : d - log1pf(expf(d));
        g_perb[b] = -ls + logf(g_negsum[b]);
    }
}

// ---------------------------------------------------------------------------
// K4: deterministic mean reduction -> scalar out
// ---------------------------------------------------------------------------
__global__ void k_final(float* __restrict__ out) {
    __shared__ float s[256];
    int t = threadIdx.x;
    float v = 0.0f;
    for (int i = t; i < BATCH; i += 256) v += g_perb[i];
    s[t] = v;
    __syncthreads();
    for (int o = 128; o; o >>= 1) {
        if (t < o) s[t] += s[t + o];
        __syncthreads();
    }
    if (t == 0) out[0] = s[0] / (float)BATCH;
}

// ---------------------------------------------------------------------------
extern "C" void kernel_launch(void* const* d_in, const int* in_sizes, int n_in,
                              void* d_out, int out_size) {
    const int*   x     = (const int*)d_in[0];
    const int*   y     = (const int*)d_in[1];
    const float* emb_v = (const float*)d_in[2];
    const float* emb_u = (const float*)d_in[3];

    k_h<<<BATCH, 128>>>(x, emb_v);
    k_u<<<(VP * KP + 255) / 256, 256>>>(emb_u);
    dim3 grid(VP / BN, BATCH / BM);  // 782 x 16
    k_gemm<<<grid, 256>>>();
    k_perb<<<BATCH / 8, 256>>>(y, emb_u);
    k_final<<<1, 256>>>((float*)d_out);
}